// round 10
// baseline (speedup 1.0000x reference)
#include <cuda_runtime.h>

// Problem constants (fixed shapes from reference: x[32,3,512,512] fp32)
#define NB        32
#define HW        262144            // 512*512
#define NBINS     256
#define F4_PER_B  (HW / 4)          // 65536 float4 groups per channel plane
#define BLK_PER_B 64
#define THREADS   256
#define NUM_PIXEL 262400.0f         // H*W + 256

// Scratch (no allocation). All state is reset within each launch so graph
// replays start clean (first launch: BSS zero; replays: stream-ordered).
__device__ int   g_hist[NB][NBINS];
__device__ int   g_batch_done[NB];   // per-batch block-completion counters
__device__ float g_partial[NB];      // per-batch entropy partial sums
__device__ int   g_final_done;       // tail-completion counter

__device__ __forceinline__ void bin4(int* sh, float4 a, float4 c, float4 d) {
    const float s = 255.0f / 3.0f;
    int i0 = (int)((a.x + c.x + d.x) * s);
    int i1 = (int)((a.y + c.y + d.y) * s);
    int i2 = (int)((a.z + c.z + d.z) * s);
    int i3 = (int)((a.w + c.w + d.w) * s);
    i0 = min(max(i0, 0), 255);
    i1 = min(max(i1, 0), 255);
    i2 = min(max(i2, 0), 255);
    i3 = min(max(i3, 0), 255);
    atomicAdd(&sh[i0], 1);
    atomicAdd(&sh[i1], 1);
    atomicAdd(&sh[i2], 1);
    atomicAdd(&sh[i3], 1);
}

__global__ void __launch_bounds__(THREADS)
fused_kernel(const float* __restrict__ x, float* __restrict__ out) {
    __shared__ int sh[NBINS];
    __shared__ int s_role;           // 0 = plain, 1 = batch tail
    const int b = blockIdx.y;
    const int t = threadIdx.x;

    for (int i = t; i < NBINS; i += THREADS) sh[i] = 0;
    __syncthreads();

    // ---- Phase 1: histogram ----
    const float4* __restrict__ p0 = (const float4*)(x + (size_t)b * 3 * HW);
    const float4* __restrict__ p1 = p0 + F4_PER_B;
    const float4* __restrict__ p2 = p1 + F4_PER_B;

    const int stride = BLK_PER_B * THREADS;  // 16384
    int i = blockIdx.x * THREADS + t;
    #pragma unroll
    for (int it = 0; it < F4_PER_B / (2 * stride); it++) {
        int j = i + stride;
        float4 a0 = p0[i], c0 = p1[i], d0 = p2[i];
        float4 a1 = p0[j], c1 = p1[j], d1 = p2[j];
        bin4(sh, a0, c0, d0);
        bin4(sh, a1, c1, d1);
        i += 2 * stride;
    }
    __syncthreads();

    for (int k = t; k < NBINS; k += THREADS) {
        int v = sh[k];
        if (v) atomicAdd(&g_hist[b][k], v);
    }
    __syncthreads();

    // ---- Phase 2: last block of THIS batch becomes its entropy tail ----
    if (t == 0) {
        __threadfence();                       // publish this block's merges
        s_role = (atomicAdd(&g_batch_done[b], 1) == BLK_PER_B - 1);
    }
    __syncthreads();
    if (!s_role) return;                       // 63 of 64 blocks retire here

    __threadfence();                           // acquire all batch-b merges

    __shared__ float warp_sum[THREADS / 32];
    __shared__ int   s_final;
    const float inv = 1.0f / NUM_PIXEL;

    int raw = __ldcg(&g_hist[b][t]);
    g_hist[b][t] = 0;                          // cleanup for next replay
    // bin-0 quirk: reference overwrites bin0 count with H*W.
    float cnt = (t == 0) ? (float)HW : (float)raw;
    float p = (cnt + 1.0f) * inv;              // '+1' smoothing
    float acc = p * __logf(p);                 // MUFU LG2; ~1e-6 rel err

    #pragma unroll
    for (int m = 16; m > 0; m >>= 1)
        acc += __shfl_xor_sync(0xFFFFFFFF, acc, m);
    if ((t & 31) == 0) warp_sum[t >> 5] = acc;
    __syncthreads();

    if (t == 0) {
        float v = 0.0f;
        #pragma unroll
        for (int w = 0; w < THREADS / 32; w++) v += warp_sum[w];
        g_partial[b] = v;                      // fixed-order -> deterministic
        g_batch_done[b] = 0;                   // reset counter for next replay
        __threadfence();                       // publish partial + resets
        s_final = (atomicAdd(&g_final_done, 1) == NB - 1);
    }
    __syncthreads();
    if (!s_final) return;                      // 31 of 32 tails retire here

    // ---- Phase 3: globally-last tail finalizes ----
    __threadfence();                           // acquire all partials
    if (t < 32) {
        float v = __ldcg(&g_partial[t]);
        #pragma unroll
        for (int m = 16; m > 0; m >>= 1)
            v += __shfl_xor_sync(0xFFFFFFFF, v, m);
        if (t == 0) {
            out[0] = v / (float)NB;
            __threadfence();
            g_final_done = 0;                  // reset for next replay
        }
    }
}

extern "C" void kernel_launch(void* const* d_in, const int* in_sizes, int n_in,
                              void* d_out, int out_size) {
    const float* x = (const float*)d_in[0];
    float* out = (float*)d_out;
    fused_kernel<<<dim3(BLK_PER_B, NB), THREADS>>>(x, out);
}

// round 11
// speedup vs baseline: 1.0884x; 1.0884x over previous
#include <cuda_runtime.h>

// Problem constants (fixed shapes from reference: x[32,3,512,512] fp32)
#define NB        32
#define HW        262144            // 512*512
#define NBINS     256
#define F4_PER_B  (HW / 4)          // 65536 float4 groups per channel plane
#define BLK_PER_B 64
#define THREADS   256
#define NUM_PIXEL 262400.0f         // H*W + 256

// Scratch (no allocation): per-batch integer histograms.
// Contract: zero at hist_kernel entry. First launch: BSS zero. Every replay:
// entropy_kernel zeroes each slot right after reading it (stream-ordered).
__device__ int g_hist[NB][NBINS];

__global__ void __launch_bounds__(THREADS)
hist_kernel(const float* __restrict__ x, float* __restrict__ out) {
    __shared__ int sh[NBINS];
    const int b = blockIdx.y;
    const int t = threadIdx.x;

    // Zero the accumulator for this launch (sole writer; entropy_kernel runs
    // stream-after). d_out is poisoned pre-timing -> must init.
    if (blockIdx.x == 0 && b == 0 && t == 0) out[0] = 0.0f;

    for (int i = t; i < NBINS; i += THREADS) sh[i] = 0;
    __syncthreads();

    // Channel planes for this batch: contiguous, HW floats apart.
    const float4* __restrict__ p0 = (const float4*)(x + (size_t)b * 3 * HW);
    const float4* __restrict__ p1 = p0 + F4_PER_B;
    const float4* __restrict__ p2 = p1 + F4_PER_B;

    const int stride = BLK_PER_B * THREADS;       // 16384
    const int base = blockIdx.x * THREADS + t;    // 4 positions per thread

    // Front-batch ALL 12 LDG.128 (MLP=12) before any dependent work, so the
    // DRAM/L2 latency is exposed once, not per-atomic-chain.
    float4 v[4][3];
    #pragma unroll
    for (int u = 0; u < 4; u++) {
        int idx = base + u * stride;
        v[u][0] = p0[idx];
        v[u][1] = p1[idx];
        v[u][2] = p2[idx];
    }

    // Compute all 16 bins, then the 16 shared atomics.
    const float s = 255.0f / 3.0f;
    #pragma unroll
    for (int u = 0; u < 4; u++) {
        float4 a = v[u][0], c = v[u][1], d = v[u][2];
        int i0 = (int)((a.x + c.x + d.x) * s);
        int i1 = (int)((a.y + c.y + d.y) * s);
        int i2 = (int)((a.z + c.z + d.z) * s);
        int i3 = (int)((a.w + c.w + d.w) * s);
        i0 = min(max(i0, 0), 255);
        i1 = min(max(i1, 0), 255);
        i2 = min(max(i2, 0), 255);
        i3 = min(max(i3, 0), 255);
        atomicAdd(&sh[i0], 1);
        atomicAdd(&sh[i1], 1);
        atomicAdd(&sh[i2], 1);
        atomicAdd(&sh[i3], 1);
    }
    __syncthreads();

    // Merge block histogram into the per-batch global one (256 atomics/block).
    atomicAdd(&g_hist[b][t], sh[t]);
}

// One block per batch: block b reads its 256-bin row (one coalesced 1KB
// burst), zeros it for the next replay, computes sum(p*log p), and
// accumulates partial/NB into out[0].
__global__ void __launch_bounds__(THREADS)
entropy_kernel(float* __restrict__ out) {
    __shared__ float warp_sum[THREADS / 32];
    const int b = blockIdx.x;
    const int t = threadIdx.x;

    const float inv = 1.0f / NUM_PIXEL;

    int raw = g_hist[b][t];
    g_hist[b][t] = 0;                      // cleanup for next replay
    // bin-0 quirk: reference overwrites bin0 count with H*W.
    float cnt = (t == 0) ? (float)HW : (float)raw;
    float p = (cnt + 1.0f) * inv;          // '+1' smoothing
    float acc = p * __logf(p);             // MUFU LG2 path; ~1e-6 rel err

    #pragma unroll
    for (int m = 16; m > 0; m >>= 1)
        acc += __shfl_xor_sync(0xFFFFFFFF, acc, m);
    if ((t & 31) == 0) warp_sum[t >> 5] = acc;
    __syncthreads();
    if (t < 32) {
        float v = (t < THREADS / 32) ? warp_sum[t] : 0.0f;
        #pragma unroll
        for (int m = 4; m > 0; m >>= 1)
            v += __shfl_xor_sync(0xFFFFFFFF, v, m);
        if (t == 0) atomicAdd(out, v * (1.0f / (float)NB));
    }
}

extern "C" void kernel_launch(void* const* d_in, const int* in_sizes, int n_in,
                              void* d_out, int out_size) {
    const float* x = (const float*)d_in[0];
    float* out = (float*)d_out;

    hist_kernel<<<dim3(BLK_PER_B, NB), THREADS>>>(x, out);
    entropy_kernel<<<NB, THREADS>>>(out);
}

// round 13
// speedup vs baseline: 1.2214x; 1.1221x over previous
#include <cuda_runtime.h>

// Problem constants (fixed shapes from reference: x[32,3,512,512] fp32)
#define NB        32
#define HW        262144            // 512*512
#define NBINS     256
#define F4_PER_B  (HW / 4)          // 65536 float4 groups per channel plane
#define BLK_PER_B 32
#define THREADS   256
#define NWARP     (THREADS / 32)    // 8
#define SUBW      257               // padded sub-hist width (bank rotation)
#define NUM_PIXEL 262400.0f         // H*W + 256

// Scratch (no allocation): per-batch integer histograms.
// Contract: zero at hist_kernel entry. First launch: BSS zero. Every replay:
// entropy_kernel zeroes each slot right after reading it (stream-ordered).
__device__ int g_hist[NB][NBINS];

__global__ void __launch_bounds__(THREADS)
hist_kernel(const float* __restrict__ x, float* __restrict__ out) {
    // Per-warp sub-histograms: no cross-warp same-address ATOMS contention;
    // 257-word stride rotates bank mapping per warp copy.
    __shared__ int sh[NWARP * SUBW];
    const int b = blockIdx.y;
    const int t = threadIdx.x;
    const int w = t >> 5;

    // Zero the accumulator for this launch (sole writer; entropy_kernel runs
    // stream-after). d_out is poisoned pre-timing -> must init.
    if (blockIdx.x == 0 && b == 0 && t == 0) out[0] = 0.0f;

    for (int i = t; i < NWARP * SUBW; i += THREADS) sh[i] = 0;
    __syncthreads();

    // Channel planes for this batch: contiguous, HW floats apart.
    const float4* __restrict__ p0 = (const float4*)(x + (size_t)b * 3 * HW);
    const float4* __restrict__ p1 = p0 + F4_PER_B;
    const float4* __restrict__ p2 = p1 + F4_PER_B;

    int* __restrict__ msh = sh + w * SUBW;
    const float s = 255.0f / 3.0f;
    const int stride = BLK_PER_B * THREADS;       // 8192
    // 8 positions per thread, processed as 2 front-batched chunks of 4
    // (12 LDG.128 in flight per chunk).
    #pragma unroll
    for (int ch = 0; ch < 2; ch++) {
        const int base = blockIdx.x * THREADS + t + ch * 4 * stride;
        float4 v[4][3];
        #pragma unroll
        for (int u = 0; u < 4; u++) {
            int idx = base + u * stride;
            v[u][0] = p0[idx];
            v[u][1] = p1[idx];
            v[u][2] = p2[idx];
        }
        #pragma unroll
        for (int u = 0; u < 4; u++) {
            float4 a = v[u][0], c = v[u][1], d = v[u][2];
            int i0 = (int)((a.x + c.x + d.x) * s);
            int i1 = (int)((a.y + c.y + d.y) * s);
            int i2 = (int)((a.z + c.z + d.z) * s);
            int i3 = (int)((a.w + c.w + d.w) * s);
            i0 = min(max(i0, 0), 255);
            i1 = min(max(i1, 0), 255);
            i2 = min(max(i2, 0), 255);
            i3 = min(max(i3, 0), 255);
            atomicAdd(&msh[i0], 1);
            atomicAdd(&msh[i1], 1);
            atomicAdd(&msh[i2], 1);
            atomicAdd(&msh[i3], 1);
        }
    }
    __syncthreads();

    // Merge: thread t owns bin t; sum the 8 warp copies, one global atomic.
    int v = 0;
    #pragma unroll
    for (int ww = 0; ww < NWARP; ww++) v += sh[ww * SUBW + t];
    atomicAdd(&g_hist[b][t], v);
}

// One block per batch: block b reads its 256-bin row (one coalesced 1KB
// burst), zeros it for the next replay, computes sum(p*log p), and
// accumulates partial/NB into out[0].
__global__ void __launch_bounds__(THREADS)
entropy_kernel(float* __restrict__ out) {
    __shared__ float warp_sum[THREADS / 32];
    const int b = blockIdx.x;
    const int t = threadIdx.x;

    const float inv = 1.0f / NUM_PIXEL;

    int raw = g_hist[b][t];
    g_hist[b][t] = 0;                      // cleanup for next replay
    // bin-0 quirk: reference overwrites bin0 count with H*W.
    float cnt = (t == 0) ? (float)HW : (float)raw;
    float p = (cnt + 1.0f) * inv;          // '+1' smoothing
    float acc = p * __logf(p);             // MUFU LG2 path; ~1e-6 rel err

    #pragma unroll
    for (int m = 16; m > 0; m >>= 1)
        acc += __shfl_xor_sync(0xFFFFFFFF, acc, m);
    if ((t & 31) == 0) warp_sum[t >> 5] = acc;
    __syncthreads();
    if (t < 32) {
        float v = (t < THREADS / 32) ? warp_sum[t] : 0.0f;
        #pragma unroll
        for (int m = 4; m > 0; m >>= 1)
            v += __shfl_xor_sync(0xFFFFFFFF, v, m);
        if (t == 0) atomicAdd(out, v * (1.0f / (float)NB));
    }
}

extern "C" void kernel_launch(void* const* d_in, const int* in_sizes, int n_in,
                              void* d_out, int out_size) {
    const float* x = (const float*)d_in[0];
    float* out = (float*)d_out;

    hist_kernel<<<dim3(BLK_PER_B, NB), THREADS>>>(x, out);
    entropy_kernel<<<NB, THREADS>>>(out);
}